// round 6
// baseline (speedup 1.0000x reference)
#include <cuda_runtime.h>
#include <cuda_fp16.h>
#include <math.h>

#define N_NODES 50000
#define N_EDGES 800000
#define ET (N_EDGES + N_NODES)   // edges + self loops = 850000
#define F_IN 128
#define H 256
#define G_GRAPHS 500
#define FC1 196
#define D_OUT 10
#define NEG 0.2f

// ---------------- scratch (static device globals; no allocation) ----------------
__device__ float g_featB[(size_t)N_NODES * H];   // aggregated output / next-layer input
__device__ __align__(16) __half g_featH[(size_t)N_NODES * H]; // fp16 h for gather
__device__ float g_as[N_NODES];                  // x . (W a_s) per node
__device__ float g_ad[N_NODES];                  // x . (W a_d) per node
__device__ float g_wvs[H];                       // W @ a_s (current layer)
__device__ float g_wvd[H];                       // W @ a_d (current layer)
__device__ float g_e[ET];                        // per-edge exp(e - m) (slow path)
__device__ int   g_deg[N_NODES];
__device__ int   g_off[N_NODES + 1];             // CSR row offsets (by dst)
__device__ int   g_pos[N_NODES];
__device__ int   g_srcs[ET];                     // CSR column indices (src node)
__device__ float g_hg[G_GRAPHS * H];             // pooled per-graph sums
__device__ float g_cnt[G_GRAPHS];
__device__ float g_fc1[G_GRAPHS * FC1];

// ================= CSR build =================
__global__ void zero_deg() {
    int i = blockIdx.x * blockDim.x + threadIdx.x;
    if (i < N_NODES) g_deg[i] = 0;
    if (i < G_GRAPHS * H) g_hg[i] = 0.f;
    if (i < G_GRAPHS) g_cnt[i] = 0.f;
}

__global__ void count_deg(const int* __restrict__ ei) {
    int e = blockIdx.x * blockDim.x + threadIdx.x;
    if (e >= ET) return;
    int d = (e < N_EDGES) ? ei[N_EDGES + e] : (e - N_EDGES);
    atomicAdd(&g_deg[d], 1);
}

__global__ void cnt_batch(const int* __restrict__ batch) {
    int i = blockIdx.x * blockDim.x + threadIdx.x;
    if (i < N_NODES) atomicAdd(&g_cnt[batch[i]], 1.f);
}

__global__ void scan_deg() {
    __shared__ int warpsums[32];
    __shared__ int s_carry;
    int tid = threadIdx.x, lane = tid & 31, wid = tid >> 5;
    if (tid == 0) s_carry = 0;
    __syncthreads();
    for (int base = 0; base < N_NODES; base += 1024) {
        int i = base + tid;
        int v = (i < N_NODES) ? g_deg[i] : 0;
        int incl = v;
#pragma unroll
        for (int o = 1; o < 32; o <<= 1) {
            int t = __shfl_up_sync(0xFFFFFFFFu, incl, o);
            if (lane >= o) incl += t;
        }
        if (lane == 31) warpsums[wid] = incl;
        __syncthreads();
        if (wid == 0) {
            int w = warpsums[lane];
#pragma unroll
            for (int o = 1; o < 32; o <<= 1) {
                int t = __shfl_up_sync(0xFFFFFFFFu, w, o);
                if (lane >= o) w += t;
            }
            warpsums[lane] = w;
        }
        __syncthreads();
        int wofs = (wid > 0) ? warpsums[wid - 1] : 0;
        int excl = s_carry + wofs + incl - v;
        if (i < N_NODES) { g_off[i] = excl; g_pos[i] = excl; }
        __syncthreads();
        if (tid == 0) s_carry += warpsums[31];
        __syncthreads();
    }
    if (tid == 0) g_off[N_NODES] = ET;
}

__global__ void scatter_edges(const int* __restrict__ ei) {
    int e = blockIdx.x * blockDim.x + threadIdx.x;
    if (e >= ET) return;
    int s, d;
    if (e < N_EDGES) { s = ei[e]; d = ei[N_EDGES + e]; }
    else             { s = d = e - N_EDGES; }
    int idx = atomicAdd(&g_pos[d], 1);
    g_srcs[idx] = s;
}

// ================= wv = W @ a  (K-length vectors; exact fp32) =================
__global__ void wv_kernel(const float* __restrict__ W, const float* __restrict__ a_s,
                          const float* __restrict__ a_d, int K) {
    int k = blockIdx.x * blockDim.x + threadIdx.x;
    if (k >= K) return;
    const float* wr = W + (size_t)k * H;
    float s = 0.f, d = 0.f;
#pragma unroll 8
    for (int j = 0; j < H; j++) { s += wr[j] * a_s[j]; d += wr[j] * a_d[j]; }
    g_wvs[k] = s;
    g_wvd[k] = d;
}

// ================= TF32 TC GEMM fused with attention dots + fp16 output =================
// C(fp16)[M,256] = A[M,K] @ W[K,256]; also g_as/g_ad = A @ wv (fp32 exact).
__device__ __forceinline__ unsigned f2tf32(float f) {
    unsigned u;
    asm("cvt.rna.tf32.f32 %0, %1;" : "=r"(u) : "f"(f));
    return u;
}

__global__ __launch_bounds__(256) void sgemm_tc(const float* __restrict__ A,
                                                const float* __restrict__ W,
                                                int M, int K) {
    __shared__ float As[16][136];   // [k][m]
    __shared__ float Bs[16][136];   // [k][n]
    int tid = threadIdx.x;
    int wid = tid >> 5, lane = tid & 31;
    int grp = lane >> 2, t4 = lane & 3;
    int wm = wid >> 2, wn = wid & 3;             // warp grid 2x4
    int row0 = blockIdx.y * 128;
    int col0 = blockIdx.x * 128;

    int arow = tid >> 2;            // 0..63 (+64 for second load)
    int acol = (tid & 3) * 4;       // 0,4,8,12
    int krow = tid >> 5;            // 0..7 (+8)
    int bcol = (tid & 31) * 4;      // 0..124

    float acc[4][4][4] = {};
    float ds0 = 0.f, dd0 = 0.f, ds1 = 0.f, dd1 = 0.f;   // attn-dot partials (2 rows)

    for (int k0 = 0; k0 < K; k0 += 16) {
        float4 wsv = *(const float4*)(g_wvs + k0 + acol);
        float4 wdv = *(const float4*)(g_wvd + k0 + acol);
        // --- load A tile (transpose to [k][m], tf32-round) + dot partials ---
#pragma unroll
        for (int h = 0; h < 2; h++) {
            int r = arow + h * 64;
            int gr = row0 + r;
            float4 av = make_float4(0.f, 0.f, 0.f, 0.f);
            if (gr < M) av = *(const float4*)(A + (size_t)gr * K + k0 + acol);
            float ps = av.x * wsv.x + av.y * wsv.y + av.z * wsv.z + av.w * wsv.w;
            float pd = av.x * wdv.x + av.y * wdv.y + av.z * wdv.z + av.w * wdv.w;
            if (h == 0) { ds0 += ps; dd0 += pd; } else { ds1 += ps; dd1 += pd; }
            As[acol + 0][r] = __uint_as_float(f2tf32(av.x));
            As[acol + 1][r] = __uint_as_float(f2tf32(av.y));
            As[acol + 2][r] = __uint_as_float(f2tf32(av.z));
            As[acol + 3][r] = __uint_as_float(f2tf32(av.w));
        }
        // --- load B tile ([k][n], tf32-round) ---
#pragma unroll
        for (int h = 0; h < 2; h++) {
            int kr = krow + h * 8;
            float4 bv = *(const float4*)(W + (size_t)(k0 + kr) * 256 + col0 + bcol);
            Bs[kr][bcol + 0] = __uint_as_float(f2tf32(bv.x));
            Bs[kr][bcol + 1] = __uint_as_float(f2tf32(bv.y));
            Bs[kr][bcol + 2] = __uint_as_float(f2tf32(bv.z));
            Bs[kr][bcol + 3] = __uint_as_float(f2tf32(bv.w));
        }
        __syncthreads();
#pragma unroll
        for (int ks = 0; ks < 16; ks += 8) {
            unsigned b0[4], b1[4];
#pragma unroll
            for (int j = 0; j < 4; j++) {
                int n = wn * 32 + j * 8 + grp;
                b0[j] = __float_as_uint(Bs[ks + t4][n]);
                b1[j] = __float_as_uint(Bs[ks + t4 + 4][n]);
            }
#pragma unroll
            for (int i = 0; i < 4; i++) {
                int m = wm * 64 + i * 16 + grp;
                unsigned a0 = __float_as_uint(As[ks + t4][m]);
                unsigned a1 = __float_as_uint(As[ks + t4][m + 8]);
                unsigned a2 = __float_as_uint(As[ks + t4 + 4][m]);
                unsigned a3 = __float_as_uint(As[ks + t4 + 4][m + 8]);
#pragma unroll
                for (int j = 0; j < 4; j++) {
                    asm("mma.sync.aligned.m16n8k8.row.col.f32.tf32.tf32.f32 "
                        "{%0,%1,%2,%3}, {%4,%5,%6,%7}, {%8,%9}, {%0,%1,%2,%3};"
                        : "+f"(acc[i][j][0]), "+f"(acc[i][j][1]),
                          "+f"(acc[i][j][2]), "+f"(acc[i][j][3])
                        : "r"(a0), "r"(a1), "r"(a2), "r"(a3),
                          "r"(b0[j]), "r"(b1[j]));
                }
            }
        }
        __syncthreads();
    }

    // --- attn-dot reduction: 4 lanes (tid&3 = 0..3) share each arow ---
    ds0 += __shfl_xor_sync(0xFFFFFFFFu, ds0, 1); ds0 += __shfl_xor_sync(0xFFFFFFFFu, ds0, 2);
    dd0 += __shfl_xor_sync(0xFFFFFFFFu, dd0, 1); dd0 += __shfl_xor_sync(0xFFFFFFFFu, dd0, 2);
    ds1 += __shfl_xor_sync(0xFFFFFFFFu, ds1, 1); ds1 += __shfl_xor_sync(0xFFFFFFFFu, ds1, 2);
    dd1 += __shfl_xor_sync(0xFFFFFFFFu, dd1, 1); dd1 += __shfl_xor_sync(0xFFFFFFFFu, dd1, 2);
    if (blockIdx.x == 0 && (tid & 3) == 0) {
        int r0 = row0 + arow;
        if (r0 < M)      { g_as[r0] = ds0;      g_ad[r0] = dd0; }
        if (r0 + 64 < M) { g_as[r0 + 64] = ds1; g_ad[r0 + 64] = dd1; }
    }

    // --- epilogue: fp16 featH only ---
#pragma unroll
    for (int i = 0; i < 4; i++) {
#pragma unroll
        for (int j = 0; j < 4; j++) {
            int row = row0 + wm * 64 + i * 16 + grp;
            int col = col0 + wn * 32 + j * 8 + t4 * 2;
            if (row < M)
                *(__half2*)(g_featH + (size_t)row * 256 + col) =
                    __floats2half2_rn(acc[i][j][0], acc[i][j][1]);
            if (row + 8 < M)
                *(__half2*)(g_featH + (size_t)(row + 8) * 256 + col) =
                    __floats2half2_rn(acc[i][j][2], acc[i][j][3]);
        }
    }
}

// ================= fused softmax + aggregate (warp per dst) =================
__device__ __forceinline__ void agg_edge(int sj, float aj, int lane, float acc[8]) {
    const uint4* hs = (const uint4*)(g_featH + (size_t)sj * H);
    uint4 q = hs[lane];
    const __half2* h2 = (const __half2*)&q;
#pragma unroll
    for (int c = 0; c < 4; c++) {
        float2 f = __half22float2(h2[c]);
        acc[c * 2 + 0] += aj * f.x;
        acc[c * 2 + 1] += aj * f.y;
    }
}

__device__ __forceinline__ void gat_attn_body(int warp, int lane, float acc[8]) {
    int beg = g_off[warp], end = g_off[warp + 1];
    int deg = end - beg;
    float ad = g_ad[warp];

    if (deg <= 32) {
        bool valid = lane < deg;
        int s = valid ? g_srcs[beg + lane] : 0;
        float e = -3.4e38f;
        if (valid) {
            e = g_as[s] + ad;
            e = (e > 0.f) ? e : NEG * e;
        }
        float m = e;
#pragma unroll
        for (int o = 16; o; o >>= 1) m = fmaxf(m, __shfl_xor_sync(0xFFFFFFFFu, m, o));
        float ex = valid ? expf(e - m) : 0.f;
        float denom = ex;
#pragma unroll
        for (int o = 16; o; o >>= 1) denom += __shfl_xor_sync(0xFFFFFFFFu, denom, o);
        float a = ex / fmaxf(denom, 1e-16f);
        for (int j = 0; j < deg; j++) {
            float aj = __shfl_sync(0xFFFFFFFFu, a, j);
            int   sj = __shfl_sync(0xFFFFFFFFu, s, j);
            agg_edge(sj, aj, lane, acc);
        }
    } else {
        float m = -3.4e38f;
        for (int i = beg + lane; i < end; i += 32) {
            float e = g_as[g_srcs[i]] + ad;
            e = (e > 0.f) ? e : NEG * e;
            m = fmaxf(m, e);
        }
#pragma unroll
        for (int o = 16; o; o >>= 1) m = fmaxf(m, __shfl_xor_sync(0xFFFFFFFFu, m, o));
        float denom = 0.f;
        for (int i = beg + lane; i < end; i += 32) {
            float e = g_as[g_srcs[i]] + ad;
            e = (e > 0.f) ? e : NEG * e;
            float ex = expf(e - m);
            g_e[i] = ex;
            denom += ex;
        }
#pragma unroll
        for (int o = 16; o; o >>= 1) denom += __shfl_xor_sync(0xFFFFFFFFu, denom, o);
        float inv = 1.f / fmaxf(denom, 1e-16f);
        for (int i0 = beg; i0 < end; i0 += 32) {
            int i = i0 + lane;
            float a = 0.f; int s = 0;
            if (i < end) { s = g_srcs[i]; a = g_e[i] * inv; }
            int cnt = min(32, end - i0);
            for (int j = 0; j < cnt; j++) {
                float aj = __shfl_sync(0xFFFFFFFFu, a, j);
                int   sj = __shfl_sync(0xFFFFFFFFu, s, j);
                agg_edge(sj, aj, lane, acc);
            }
        }
    }
}

// layers 1-2: write featB (fp32) for next GEMM
__global__ void gat_attn(const float* __restrict__ bias) {
    int warp = (blockIdx.x * blockDim.x + threadIdx.x) >> 5;
    int lane = threadIdx.x & 31;
    if (warp >= N_NODES) return;
    float acc[8] = {};
    gat_attn_body(warp, lane, acc);
    float* out = g_featB + (size_t)warp * H + lane * 8;
    const float* bp = bias + lane * 8;
    float4 o0, o1;
    o0.x = fmaxf(acc[0] + bp[0], 0.f); o0.y = fmaxf(acc[1] + bp[1], 0.f);
    o0.z = fmaxf(acc[2] + bp[2], 0.f); o0.w = fmaxf(acc[3] + bp[3], 0.f);
    o1.x = fmaxf(acc[4] + bp[4], 0.f); o1.y = fmaxf(acc[5] + bp[5], 0.f);
    o1.z = fmaxf(acc[6] + bp[6], 0.f); o1.w = fmaxf(acc[7] + bp[7], 0.f);
    *(float4*)out = o0;
    *(float4*)(out + 4) = o1;
}

// layer 3: pool directly into g_hg (skip featB entirely)
__global__ void gat_attn_pool(const float* __restrict__ bias, const int* __restrict__ batch) {
    int warp = (blockIdx.x * blockDim.x + threadIdx.x) >> 5;
    int lane = threadIdx.x & 31;
    if (warp >= N_NODES) return;
    float acc[8] = {};
    gat_attn_body(warp, lane, acc);
    int g = batch[warp];
    float* hg = g_hg + (size_t)g * H + lane * 8;
    const float* bp = bias + lane * 8;
#pragma unroll
    for (int c = 0; c < 8; c++)
        atomicAdd(&hg[c], fmaxf(acc[c] + bp[c], 0.f));
}

// ================= MLP head =================
__global__ void fc1_kernel(const float* __restrict__ w, const float* __restrict__ b) {
    __shared__ float sh[H];
    int g = blockIdx.x;
    float c = fmaxf(g_cnt[g], 1.f);
    sh[threadIdx.x] = g_hg[(size_t)g * H + threadIdx.x] / c;
    __syncthreads();
    int j = threadIdx.x;
    if (j < FC1) {
        float acc = b[j];
#pragma unroll 8
        for (int k = 0; k < H; k++)
            acc += sh[k] * w[(size_t)k * FC1 + j];
        g_fc1[(size_t)g * FC1 + j] = fmaxf(acc, 0.f);
    }
}

__global__ void fc2_kernel(const float* __restrict__ w, const float* __restrict__ b,
                           float* __restrict__ out) {
    int g = blockIdx.x;
    int o = threadIdx.x;
    if (o >= D_OUT) return;
    float acc = b[o];
#pragma unroll 4
    for (int k = 0; k < FC1; k++)
        acc += g_fc1[(size_t)g * FC1 + k] * w[(size_t)k * D_OUT + o];
    out[(size_t)g * D_OUT + o] = acc;
}

// ================= host =================
extern "C" void kernel_launch(void* const* d_in, const int* in_sizes, int n_in,
                              void* d_out, int out_size) {
    const float* x     = (const float*)d_in[0];
    const int*   ei    = (const int*)d_in[1];
    const int*   batch = (const int*)d_in[2];
    const float* W1 = (const float*)d_in[3];
    const float* a1s = (const float*)d_in[4];
    const float* a1d = (const float*)d_in[5];
    const float* b1 = (const float*)d_in[6];
    const float* W2 = (const float*)d_in[7];
    const float* a2s = (const float*)d_in[8];
    const float* a2d = (const float*)d_in[9];
    const float* b2 = (const float*)d_in[10];
    const float* W3 = (const float*)d_in[11];
    const float* a3s = (const float*)d_in[12];
    const float* a3d = (const float*)d_in[13];
    const float* b3 = (const float*)d_in[14];
    const float* fc1_w = (const float*)d_in[15];
    const float* fc1_b = (const float*)d_in[16];
    const float* fc2_w = (const float*)d_in[17];
    const float* fc2_b = (const float*)d_in[18];

    float* featB = nullptr;
    cudaGetSymbolAddress((void**)&featB, g_featB);

    dim3 gemmGrid(2, (N_NODES + 127) / 128);
    int edgeBlocks = (ET + 255) / 256;
    int nodeBlocksW = ((size_t)N_NODES * 32 + 255) / 256;

    // ---- CSR by dst + pooling counters ----
    // G_GRAPHS*H = 128000 > N_NODES = 50000: one grid covers all three zero ranges.
    zero_deg<<<(G_GRAPHS * H + 255) / 256, 256>>>();
    count_deg<<<edgeBlocks, 256>>>(ei);
    cnt_batch<<<(N_NODES + 255) / 256, 256>>>(batch);
    scan_deg<<<1, 1024>>>();
    scatter_edges<<<edgeBlocks, 256>>>(ei);

    // ---- layer 1 (K = F_IN) ----
    wv_kernel<<<1, F_IN>>>(W1, a1s, a1d, F_IN);
    sgemm_tc<<<gemmGrid, 256>>>(x, W1, N_NODES, F_IN);
    gat_attn<<<nodeBlocksW, 256>>>(b1);

    // ---- layer 2 ----
    wv_kernel<<<1, H>>>(W2, a2s, a2d, H);
    sgemm_tc<<<gemmGrid, 256>>>(featB, W2, N_NODES, H);
    gat_attn<<<nodeBlocksW, 256>>>(b2);

    // ---- layer 3 (pool fused) ----
    wv_kernel<<<1, H>>>(W3, a3s, a3d, H);
    sgemm_tc<<<gemmGrid, 256>>>(featB, W3, N_NODES, H);
    gat_attn_pool<<<nodeBlocksW, 256>>>(b3, batch);

    // ---- MLP head ----
    fc1_kernel<<<G_GRAPHS, H>>>(fc1_w, fc1_b);
    fc2_kernel<<<G_GRAPHS, 32>>>(fc2_w, fc2_b, (float*)d_out);
}

// round 7
// speedup vs baseline: 1.2405x; 1.2405x over previous
#include <cuda_runtime.h>
#include <cuda_fp16.h>
#include <math.h>

#define N_NODES 50000
#define N_EDGES 800000
#define ET (N_EDGES + N_NODES)   // edges + self loops = 850000
#define F_IN 128
#define H 256
#define G_GRAPHS 500
#define FC1 196
#define D_OUT 10
#define NEG 0.2f
#define NB_SCAN ((N_NODES + 1023) / 1024)   // 49 scan blocks

// ---------------- scratch (static device globals; no allocation) ----------------
__device__ float g_featB[(size_t)N_NODES * H];   // aggregated output / next-layer input
__device__ __align__(16) __half g_featH[(size_t)N_NODES * H]; // fp16 h for gather
__device__ float g_as[N_NODES];                  // x . (W a_s) per node
__device__ float g_ad[N_NODES];                  // x . (W a_d) per node
__device__ float g_wvs[H];                       // W @ a_s (current layer)
__device__ float g_wvd[H];                       // W @ a_d (current layer)
__device__ float g_e[ET];                        // per-edge exp(e - m) (slow path)
__device__ int   g_deg[N_NODES];
__device__ int   g_off[N_NODES + 1];             // CSR row offsets (by dst)
__device__ int   g_pos[N_NODES];
__device__ int   g_srcs[ET];                     // CSR column indices (src node)
__device__ int   g_bsum[NB_SCAN];                // scan block totals
__device__ int   g_bpre[NB_SCAN];                // scan block prefix (exclusive)
__device__ float g_hg[G_GRAPHS * H];             // pooled per-graph sums
__device__ float g_cnt[G_GRAPHS];
__device__ float g_fc1[G_GRAPHS * FC1];

// ================= CSR build =================
__global__ void zero_deg() {
    int i = blockIdx.x * blockDim.x + threadIdx.x;
    if (i < N_NODES) g_deg[i] = 0;
    if (i < G_GRAPHS * H) g_hg[i] = 0.f;
    if (i < G_GRAPHS) g_cnt[i] = 0.f;
}

__global__ void count_deg(const int* __restrict__ ei) {
    int e = blockIdx.x * blockDim.x + threadIdx.x;
    if (e >= ET) return;
    int d = (e < N_EDGES) ? ei[N_EDGES + e] : (e - N_EDGES);
    atomicAdd(&g_deg[d], 1);
}

__global__ void cnt_batch(const int* __restrict__ batch) {
    int i = blockIdx.x * blockDim.x + threadIdx.x;
    if (i < N_NODES) atomicAdd(&g_cnt[batch[i]], 1.f);
}

// --- 3-phase exclusive scan of g_deg: local scan / block-sum scan / add offsets ---
__global__ __launch_bounds__(1024) void scan_local() {
    __shared__ int ws[32];
    int tid = threadIdx.x, lane = tid & 31, wid = tid >> 5;
    int i = blockIdx.x * 1024 + tid;
    int v = (i < N_NODES) ? g_deg[i] : 0;
    int incl = v;
#pragma unroll
    for (int o = 1; o < 32; o <<= 1) {
        int t = __shfl_up_sync(0xFFFFFFFFu, incl, o);
        if (lane >= o) incl += t;
    }
    if (lane == 31) ws[wid] = incl;
    __syncthreads();
    if (wid == 0) {
        int w = ws[lane];
#pragma unroll
        for (int o = 1; o < 32; o <<= 1) {
            int t = __shfl_up_sync(0xFFFFFFFFu, w, o);
            if (lane >= o) w += t;
        }
        ws[lane] = w;
    }
    __syncthreads();
    int excl = (wid ? ws[wid - 1] : 0) + incl - v;
    if (i < N_NODES) g_off[i] = excl;          // block-local exclusive
    if (tid == 0) g_bsum[blockIdx.x] = ws[31]; // block total
}

__global__ void scan_bsums() {
    __shared__ int sh[64];
    int tid = threadIdx.x;
    int v = (tid < NB_SCAN) ? g_bsum[tid] : 0;
    sh[tid] = v;
    __syncthreads();
#pragma unroll
    for (int o = 1; o < 64; o <<= 1) {
        int t = (tid >= o) ? sh[tid - o] : 0;
        __syncthreads();
        sh[tid] += t;
        __syncthreads();
    }
    if (tid < NB_SCAN) g_bpre[tid] = sh[tid] - v;  // exclusive
}

__global__ void scan_add() {
    int i = blockIdx.x * blockDim.x + threadIdx.x;
    if (i == 0) g_off[N_NODES] = ET;
    if (i < N_NODES) {
        int o = g_off[i] + g_bpre[i >> 10];
        g_off[i] = o;
        g_pos[i] = o;
    }
}

__global__ void scatter_edges(const int* __restrict__ ei) {
    int e = blockIdx.x * blockDim.x + threadIdx.x;
    if (e >= ET) return;
    int s, d;
    if (e < N_EDGES) { s = ei[e]; d = ei[N_EDGES + e]; }
    else             { s = d = e - N_EDGES; }
    int idx = atomicAdd(&g_pos[d], 1);
    g_srcs[idx] = s;
}

// ================= wv = W @ a  (warp per output k, coalesced row reads) =================
__global__ void wv_kernel(const float* __restrict__ W, const float* __restrict__ a_s,
                          const float* __restrict__ a_d, int K) {
    int k = (blockIdx.x * blockDim.x + threadIdx.x) >> 5;   // output index
    int lane = threadIdx.x & 31;
    if (k >= K) return;
    const float4* wr  = (const float4*)(W + (size_t)k * H);
    const float4* sa  = (const float4*)a_s;
    const float4* da  = (const float4*)a_d;
    float4 w0 = wr[lane], w1 = wr[lane + 32];
    float4 s0 = sa[lane], s1 = sa[lane + 32];
    float4 d0 = da[lane], d1 = da[lane + 32];
    float s = w0.x * s0.x + w0.y * s0.y + w0.z * s0.z + w0.w * s0.w
            + w1.x * s1.x + w1.y * s1.y + w1.z * s1.z + w1.w * s1.w;
    float d = w0.x * d0.x + w0.y * d0.y + w0.z * d0.z + w0.w * d0.w
            + w1.x * d1.x + w1.y * d1.y + w1.z * d1.z + w1.w * d1.w;
#pragma unroll
    for (int o = 16; o; o >>= 1) {
        s += __shfl_down_sync(0xFFFFFFFFu, s, o);
        d += __shfl_down_sync(0xFFFFFFFFu, d, o);
    }
    if (lane == 0) { g_wvs[k] = s; g_wvd[k] = d; }
}

// ================= TF32 TC GEMM fused with attention dots + fp16 output =================
// C(fp16)[M,256] = A[M,K] @ W[K,256]; also g_as/g_ad = A @ wv (fp32 exact).
__device__ __forceinline__ unsigned f2tf32(float f) {
    unsigned u;
    asm("cvt.rna.tf32.f32 %0, %1;" : "=r"(u) : "f"(f));
    return u;
}

__global__ __launch_bounds__(256) void sgemm_tc(const float* __restrict__ A,
                                                const float* __restrict__ W,
                                                int M, int K) {
    __shared__ float As[16][136];   // [k][m]
    __shared__ float Bs[16][136];   // [k][n]
    int tid = threadIdx.x;
    int wid = tid >> 5, lane = tid & 31;
    int grp = lane >> 2, t4 = lane & 3;
    int wm = wid >> 2, wn = wid & 3;             // warp grid 2x4
    int row0 = blockIdx.y * 128;
    int col0 = blockIdx.x * 128;

    int arow = tid >> 2;            // 0..63 (+64 for second load)
    int acol = (tid & 3) * 4;       // 0,4,8,12
    int krow = tid >> 5;            // 0..7 (+8)
    int bcol = (tid & 31) * 4;      // 0..124

    float acc[4][4][4] = {};
    float ds0 = 0.f, dd0 = 0.f, ds1 = 0.f, dd1 = 0.f;   // attn-dot partials (2 rows)

    for (int k0 = 0; k0 < K; k0 += 16) {
        float4 wsv = *(const float4*)(g_wvs + k0 + acol);
        float4 wdv = *(const float4*)(g_wvd + k0 + acol);
        // --- load A tile (transpose to [k][m], tf32-round) + dot partials ---
#pragma unroll
        for (int h = 0; h < 2; h++) {
            int r = arow + h * 64;
            int gr = row0 + r;
            float4 av = make_float4(0.f, 0.f, 0.f, 0.f);
            if (gr < M) av = *(const float4*)(A + (size_t)gr * K + k0 + acol);
            float ps = av.x * wsv.x + av.y * wsv.y + av.z * wsv.z + av.w * wsv.w;
            float pd = av.x * wdv.x + av.y * wdv.y + av.z * wdv.z + av.w * wdv.w;
            if (h == 0) { ds0 += ps; dd0 += pd; } else { ds1 += ps; dd1 += pd; }
            As[acol + 0][r] = __uint_as_float(f2tf32(av.x));
            As[acol + 1][r] = __uint_as_float(f2tf32(av.y));
            As[acol + 2][r] = __uint_as_float(f2tf32(av.z));
            As[acol + 3][r] = __uint_as_float(f2tf32(av.w));
        }
        // --- load B tile ([k][n], tf32-round) ---
#pragma unroll
        for (int h = 0; h < 2; h++) {
            int kr = krow + h * 8;
            float4 bv = *(const float4*)(W + (size_t)(k0 + kr) * 256 + col0 + bcol);
            Bs[kr][bcol + 0] = __uint_as_float(f2tf32(bv.x));
            Bs[kr][bcol + 1] = __uint_as_float(f2tf32(bv.y));
            Bs[kr][bcol + 2] = __uint_as_float(f2tf32(bv.z));
            Bs[kr][bcol + 3] = __uint_as_float(f2tf32(bv.w));
        }
        __syncthreads();
#pragma unroll
        for (int ks = 0; ks < 16; ks += 8) {
            unsigned b0[4], b1[4];
#pragma unroll
            for (int j = 0; j < 4; j++) {
                int n = wn * 32 + j * 8 + grp;
                b0[j] = __float_as_uint(Bs[ks + t4][n]);
                b1[j] = __float_as_uint(Bs[ks + t4 + 4][n]);
            }
#pragma unroll
            for (int i = 0; i < 4; i++) {
                int m = wm * 64 + i * 16 + grp;
                unsigned a0 = __float_as_uint(As[ks + t4][m]);
                unsigned a1 = __float_as_uint(As[ks + t4][m + 8]);
                unsigned a2 = __float_as_uint(As[ks + t4 + 4][m]);
                unsigned a3 = __float_as_uint(As[ks + t4 + 4][m + 8]);
#pragma unroll
                for (int j = 0; j < 4; j++) {
                    asm("mma.sync.aligned.m16n8k8.row.col.f32.tf32.tf32.f32 "
                        "{%0,%1,%2,%3}, {%4,%5,%6,%7}, {%8,%9}, {%0,%1,%2,%3};"
                        : "+f"(acc[i][j][0]), "+f"(acc[i][j][1]),
                          "+f"(acc[i][j][2]), "+f"(acc[i][j][3])
                        : "r"(a0), "r"(a1), "r"(a2), "r"(a3),
                          "r"(b0[j]), "r"(b1[j]));
                }
            }
        }
        __syncthreads();
    }

    // --- attn-dot reduction: 4 lanes (tid&3 = 0..3) share each arow ---
    ds0 += __shfl_xor_sync(0xFFFFFFFFu, ds0, 1); ds0 += __shfl_xor_sync(0xFFFFFFFFu, ds0, 2);
    dd0 += __shfl_xor_sync(0xFFFFFFFFu, dd0, 1); dd0 += __shfl_xor_sync(0xFFFFFFFFu, dd0, 2);
    ds1 += __shfl_xor_sync(0xFFFFFFFFu, ds1, 1); ds1 += __shfl_xor_sync(0xFFFFFFFFu, ds1, 2);
    dd1 += __shfl_xor_sync(0xFFFFFFFFu, dd1, 1); dd1 += __shfl_xor_sync(0xFFFFFFFFu, dd1, 2);
    if (blockIdx.x == 0 && (tid & 3) == 0) {
        int r0 = row0 + arow;
        if (r0 < M)      { g_as[r0] = ds0;      g_ad[r0] = dd0; }
        if (r0 + 64 < M) { g_as[r0 + 64] = ds1; g_ad[r0 + 64] = dd1; }
    }

    // --- epilogue: fp16 featH only ---
#pragma unroll
    for (int i = 0; i < 4; i++) {
#pragma unroll
        for (int j = 0; j < 4; j++) {
            int row = row0 + wm * 64 + i * 16 + grp;
            int col = col0 + wn * 32 + j * 8 + t4 * 2;
            if (row < M)
                *(__half2*)(g_featH + (size_t)row * 256 + col) =
                    __floats2half2_rn(acc[i][j][0], acc[i][j][1]);
            if (row + 8 < M)
                *(__half2*)(g_featH + (size_t)(row + 8) * 256 + col) =
                    __floats2half2_rn(acc[i][j][2], acc[i][j][3]);
        }
    }
}

// ================= fused softmax + aggregate (warp per dst) =================
__device__ __forceinline__ void agg_edge(int sj, float aj, int lane, float acc[8]) {
    const uint4* hs = (const uint4*)(g_featH + (size_t)sj * H);
    uint4 q = hs[lane];
    const __half2* h2 = (const __half2*)&q;
#pragma unroll
    for (int c = 0; c < 4; c++) {
        float2 f = __half22float2(h2[c]);
        acc[c * 2 + 0] += aj * f.x;
        acc[c * 2 + 1] += aj * f.y;
    }
}

__device__ __forceinline__ void gat_attn_body(int warp, int lane, float acc[8]) {
    int beg = g_off[warp], end = g_off[warp + 1];
    int deg = end - beg;
    float ad = g_ad[warp];

    if (deg <= 32) {
        bool valid = lane < deg;
        int s = valid ? g_srcs[beg + lane] : 0;
        float e = -3.4e38f;
        if (valid) {
            e = g_as[s] + ad;
            e = (e > 0.f) ? e : NEG * e;
        }
        float m = e;
#pragma unroll
        for (int o = 16; o; o >>= 1) m = fmaxf(m, __shfl_xor_sync(0xFFFFFFFFu, m, o));
        float ex = valid ? expf(e - m) : 0.f;
        float denom = ex;
#pragma unroll
        for (int o = 16; o; o >>= 1) denom += __shfl_xor_sync(0xFFFFFFFFu, denom, o);
        float a = ex / fmaxf(denom, 1e-16f);
        for (int j = 0; j < deg; j++) {
            float aj = __shfl_sync(0xFFFFFFFFu, a, j);
            int   sj = __shfl_sync(0xFFFFFFFFu, s, j);
            agg_edge(sj, aj, lane, acc);
        }
    } else {
        float m = -3.4e38f;
        for (int i = beg + lane; i < end; i += 32) {
            float e = g_as[g_srcs[i]] + ad;
            e = (e > 0.f) ? e : NEG * e;
            m = fmaxf(m, e);
        }
#pragma unroll
        for (int o = 16; o; o >>= 1) m = fmaxf(m, __shfl_xor_sync(0xFFFFFFFFu, m, o));
        float denom = 0.f;
        for (int i = beg + lane; i < end; i += 32) {
            float e = g_as[g_srcs[i]] + ad;
            e = (e > 0.f) ? e : NEG * e;
            float ex = expf(e - m);
            g_e[i] = ex;
            denom += ex;
        }
#pragma unroll
        for (int o = 16; o; o >>= 1) denom += __shfl_xor_sync(0xFFFFFFFFu, denom, o);
        float inv = 1.f / fmaxf(denom, 1e-16f);
        for (int i0 = beg; i0 < end; i0 += 32) {
            int i = i0 + lane;
            float a = 0.f; int s = 0;
            if (i < end) { s = g_srcs[i]; a = g_e[i] * inv; }
            int cnt = min(32, end - i0);
            for (int j = 0; j < cnt; j++) {
                float aj = __shfl_sync(0xFFFFFFFFu, a, j);
                int   sj = __shfl_sync(0xFFFFFFFFu, s, j);
                agg_edge(sj, aj, lane, acc);
            }
        }
    }
}

// layers 1-2: write featB (fp32) for next GEMM
__global__ void gat_attn(const float* __restrict__ bias) {
    int warp = (blockIdx.x * blockDim.x + threadIdx.x) >> 5;
    int lane = threadIdx.x & 31;
    if (warp >= N_NODES) return;
    float acc[8] = {};
    gat_attn_body(warp, lane, acc);
    float* out = g_featB + (size_t)warp * H + lane * 8;
    const float* bp = bias + lane * 8;
    float4 o0, o1;
    o0.x = fmaxf(acc[0] + bp[0], 0.f); o0.y = fmaxf(acc[1] + bp[1], 0.f);
    o0.z = fmaxf(acc[2] + bp[2], 0.f); o0.w = fmaxf(acc[3] + bp[3], 0.f);
    o1.x = fmaxf(acc[4] + bp[4], 0.f); o1.y = fmaxf(acc[5] + bp[5], 0.f);
    o1.z = fmaxf(acc[6] + bp[6], 0.f); o1.w = fmaxf(acc[7] + bp[7], 0.f);
    *(float4*)out = o0;
    *(float4*)(out + 4) = o1;
}

// layer 3: pool directly into g_hg (skip featB entirely)
__global__ void gat_attn_pool(const float* __restrict__ bias, const int* __restrict__ batch) {
    int warp = (blockIdx.x * blockDim.x + threadIdx.x) >> 5;
    int lane = threadIdx.x & 31;
    if (warp >= N_NODES) return;
    float acc[8] = {};
    gat_attn_body(warp, lane, acc);
    int g = batch[warp];
    float* hg = g_hg + (size_t)g * H + lane * 8;
    const float* bp = bias + lane * 8;
#pragma unroll
    for (int c = 0; c < 8; c++)
        atomicAdd(&hg[c], fmaxf(acc[c] + bp[c], 0.f));
}

// ================= MLP head =================
__global__ void fc1_kernel(const float* __restrict__ w, const float* __restrict__ b) {
    __shared__ float sh[H];
    int g = blockIdx.x;
    float c = fmaxf(g_cnt[g], 1.f);
    sh[threadIdx.x] = g_hg[(size_t)g * H + threadIdx.x] / c;
    __syncthreads();
    int j = threadIdx.x;
    if (j < FC1) {
        float acc = b[j];
#pragma unroll 8
        for (int k = 0; k < H; k++)
            acc += sh[k] * w[(size_t)k * FC1 + j];
        g_fc1[(size_t)g * FC1 + j] = fmaxf(acc, 0.f);
    }
}

__global__ void fc2_kernel(const float* __restrict__ w, const float* __restrict__ b,
                           float* __restrict__ out) {
    int g = blockIdx.x;
    int o = threadIdx.x;
    if (o >= D_OUT) return;
    float acc = b[o];
#pragma unroll 4
    for (int k = 0; k < FC1; k++)
        acc += g_fc1[(size_t)g * FC1 + k] * w[(size_t)k * D_OUT + o];
    out[(size_t)g * D_OUT + o] = acc;
}

// ================= host =================
extern "C" void kernel_launch(void* const* d_in, const int* in_sizes, int n_in,
                              void* d_out, int out_size) {
    const float* x     = (const float*)d_in[0];
    const int*   ei    = (const int*)d_in[1];
    const int*   batch = (const int*)d_in[2];
    const float* W1 = (const float*)d_in[3];
    const float* a1s = (const float*)d_in[4];
    const float* a1d = (const float*)d_in[5];
    const float* b1 = (const float*)d_in[6];
    const float* W2 = (const float*)d_in[7];
    const float* a2s = (const float*)d_in[8];
    const float* a2d = (const float*)d_in[9];
    const float* b2 = (const float*)d_in[10];
    const float* W3 = (const float*)d_in[11];
    const float* a3s = (const float*)d_in[12];
    const float* a3d = (const float*)d_in[13];
    const float* b3 = (const float*)d_in[14];
    const float* fc1_w = (const float*)d_in[15];
    const float* fc1_b = (const float*)d_in[16];
    const float* fc2_w = (const float*)d_in[17];
    const float* fc2_b = (const float*)d_in[18];

    float* featB = nullptr;
    cudaGetSymbolAddress((void**)&featB, g_featB);

    dim3 gemmGrid(2, (N_NODES + 127) / 128);
    int edgeBlocks = (ET + 255) / 256;
    int nodeBlocksW = ((size_t)N_NODES * 32 + 255) / 256;

    // ---- CSR by dst + pooling counters ----
    // G_GRAPHS*H = 128000 > N_NODES = 50000: one grid covers all three zero ranges.
    zero_deg<<<(G_GRAPHS * H + 255) / 256, 256>>>();
    count_deg<<<edgeBlocks, 256>>>(ei);
    cnt_batch<<<(N_NODES + 255) / 256, 256>>>(batch);
    scan_local<<<NB_SCAN, 1024>>>();
    scan_bsums<<<1, 64>>>();
    scan_add<<<(N_NODES + 255) / 256, 256>>>();
    scatter_edges<<<edgeBlocks, 256>>>(ei);

    // ---- layer 1 (K = F_IN) ----
    wv_kernel<<<F_IN / 8, 256>>>(W1, a1s, a1d, F_IN);
    sgemm_tc<<<gemmGrid, 256>>>(x, W1, N_NODES, F_IN);
    gat_attn<<<nodeBlocksW, 256>>>(b1);

    // ---- layer 2 ----
    wv_kernel<<<H / 8, 256>>>(W2, a2s, a2d, H);
    sgemm_tc<<<gemmGrid, 256>>>(featB, W2, N_NODES, H);
    gat_attn<<<nodeBlocksW, 256>>>(b2);

    // ---- layer 3 (pool fused) ----
    wv_kernel<<<H / 8, 256>>>(W3, a3s, a3d, H);
    sgemm_tc<<<gemmGrid, 256>>>(featB, W3, N_NODES, H);
    gat_attn_pool<<<nodeBlocksW, 256>>>(b3, batch);

    // ---- MLP head ----
    fc1_kernel<<<G_GRAPHS, H>>>(fc1_w, fc1_b);
    fc2_kernel<<<G_GRAPHS, 32>>>(fc2_w, fc2_b, (float*)d_out);
}